// round 2
// baseline (speedup 1.0000x reference)
#include <cuda_runtime.h>
#include <math.h>

#define Ng 96    // number of graphs (both S and T)
#define nS 48    // nodes per graph
#define RK 16    // low rank
#define Dd 128   // feature dim
#define Cc 10    // classes
#define TILE 96  // tile = 2 graphs per side
#define PLD 132  // padded smem row stride (floats)
#define NSS 1176 // 48*49/2 upper-tri 96-tiles
#define NST 2304 // 48*48 ST tiles

// ---------- persistent scratch ----------
__device__ float g_d0S[Ng][nS];
__device__ float g_d0T[Ng][nS];
__device__ float g_w[Ng][nS];
__device__ float g_z[Ng][nS];
__device__ float g_KST[Ng * Ng];

// ---------- f32x2 packed helpers ----------
__device__ __forceinline__ unsigned long long pk2(float lo, float hi) {
    unsigned long long d;
    asm("mov.b64 %0, {%1, %2};" : "=l"(d) : "f"(lo), "f"(hi));
    return d;
}
__device__ __forceinline__ void fma2(unsigned long long& d, unsigned long long a,
                                     unsigned long long b) {
    asm("fma.rn.f32x2 %0, %1, %2, %3;" : "=l"(d) : "l"(a), "l"(b), "l"(d));
}
__device__ __forceinline__ void unpk2(float& lo, float& hi, unsigned long long v) {
    asm("mov.b64 {%0, %1}, %2;" : "=f"(lo), "=f"(hi) : "l"(v));
}

// ============================================================
// Kernel A: per-graph precompute (unchanged from R1)
// ============================================================
__global__ void precompute_kernel(const float* __restrict__ U,
                                  const float* __restrict__ V,
                                  const float* __restrict__ XS,
                                  const float* __restrict__ AT,
                                  const float* __restrict__ XT) {
    int g = blockIdx.x, t = threadIdx.x;
    const float* Ug = U + (size_t)g * nS * RK;
    const float* Vg = V + (size_t)g * RK * nS;
    const float* Ag = AT + (size_t)g * nS * nS;

    __shared__ float VU[RK][RK];
    __shared__ float u1[RK], u2a[RK], u2[RK], sv[nS];

    if (t < nS) {
        const float4* row = (const float4*)(XS + (size_t)g * nS * Dd + t * Dd);
        float acc = 0.f;
        #pragma unroll
        for (int k = 0; k < Dd / 4; k++) {
            float4 v = row[k];
            acc += v.x * v.x + v.y * v.y + v.z * v.z + v.w * v.w;
        }
        g_d0S[g][t] = sqrtf(acc + 1e-4f);
    } else if (t < 2 * nS) {
        int r = t - nS;
        const float4* row = (const float4*)(XT + (size_t)g * nS * Dd + r * Dd);
        float acc = 0.f;
        #pragma unroll
        for (int k = 0; k < Dd / 4; k++) {
            float4 v = row[k];
            acc += v.x * v.x + v.y * v.y + v.z * v.z + v.w * v.w;
        }
        g_d0T[g][r] = sqrtf(acc + 1e-4f);
    }

    for (int e = t; e < RK * RK; e += blockDim.x) {
        int i = e / RK, j = e % RK;
        float acc = 0.f;
        for (int a = 0; a < nS; a++) acc += Vg[i * nS + a] * Ug[a * RK + j];
        VU[i][j] = acc;
    }
    __syncthreads();

    if (t < RK) {
        float acc = 0.f;
        for (int a = 0; a < nS; a++) acc += Ug[a * RK + t];
        u1[t] = acc;
    } else if (t < RK + nS) {
        int i = t - RK;
        float acc = 0.f;
        for (int j = 0; j < nS; j++) acc += Ag[j * nS + i];
        sv[i] = acc + 1e-4f;
    }
    __syncthreads();
    if (t < RK) {
        float acc = 0.f;
        for (int r = 0; r < RK; r++) acc += VU[r][t] * u1[r];
        u2a[t] = acc;
    }
    __syncthreads();
    if (t < RK) {
        float acc = 0.f;
        for (int r = 0; r < RK; r++) acc += VU[r][t] * u2a[r];
        u2[t] = acc;
    }
    __syncthreads();
    if (t < nS) {
        float acc = 0.f;
        for (int r = 0; r < RK; r++) acc += Vg[r * nS + t] * u2[r];
        g_w[g][t] = acc;
    } else if (t < 2 * nS) {
        int i = t - nS;
        float acc = 0.f;
        for (int j = 0; j < nS; j++) acc += Ag[j * nS + i] * sv[j];
        g_z[g][i] = acc + 1e-4f * sv[i];
    }
}

// ============================================================
// NTK elementwise recursion (2 MLP layers)
// ============================================================
__device__ __forceinline__ float ntk_eval(float dot, float da, float db, float c1) {
    const float PI_F = 3.14159265358979323846f;
    float p = da * db;
    float sigma = dot + 1e-4f;
    float ntk = sigma;
    float tmp = p + 1e-6f;
    #pragma unroll
    for (int l = 0; l < 2; l++) {
        float si = __fdividef(sigma, tmp);
        si = fminf(fmaxf(si, -0.9999f), 0.9999f);
        float th = acosf(si);
        float pit = PI_F - th;
        float s = (si * pit + sqrtf(fmaxf(1.f - si * si, 0.f))) * (1.f / PI_F);
        ntk = ntk * (pit * (1.f / PI_F)) + s;
        sigma = s * tmp;
        tmp = fmaf(c1, p, 1e-6f);  // diag[1]^2 = c1 * diag[0]^2
    }
    return ntk;
}

// ============================================================
// Kernel B: 96x96 tile kernel over flattened (4608 x 4608) sigma.
// Each block: 2x2 graph pairs. SS tiles upper-triangular, ST full.
// 6x6 per-thread register tile, packed f32x2 FFMA.
// ============================================================
__global__ void __launch_bounds__(256, 2)
tile_kernel(const float* __restrict__ XS, const float* __restrict__ XT,
            float* __restrict__ KSS) {
    int bid = blockIdx.x;
    int ti, tj, isST;
    if (bid < NSS) {
        isST = 0;
        int rem = bid, cnt = 48;
        ti = 0;
        while (rem >= cnt) { rem -= cnt; ti++; cnt--; }
        tj = ti + rem;
    } else {
        isST = 1;
        int r = bid - NSS;
        ti = r / 48;
        tj = r - ti * 48;
    }

    extern __shared__ float sm[];
    float* XL = sm;                      // 96 x 132
    float* XR = XL + TILE * PLD;         // 96 x 132
    float* dL = XR + TILE * PLD;         // 96
    float* dR = dL + TILE;
    float* vL = dR + TILE;
    float* vR = vL + TILE;
    float* parr = vR + TILE;             // 256

    int t = threadIdx.x;
    const float* XLp = XS + (size_t)(2 * ti) * nS * Dd;
    const float* XRp = (isST ? XT : XS) + (size_t)(2 * tj) * nS * Dd;

    for (int i = t; i < TILE * Dd / 4; i += 256) {
        int row = i >> 5, kq = i & 31;
        float4 v = ((const float4*)XLp)[i];
        *(float4*)(XL + row * PLD + kq * 4) = v;
        float4 w = ((const float4*)XRp)[i];
        *(float4*)(XR + row * PLD + kq * 4) = w;
    }
    if (t < TILE) {
        dL[t] = ((const float*)g_d0S)[2 * ti * nS + t];
        vL[t] = ((const float*)g_w)[2 * ti * nS + t];
        const float* dsrc = isST ? (const float*)g_d0T : (const float*)g_d0S;
        const float* vsrc = isST ? (const float*)g_z : (const float*)g_w;
        dR[t] = dsrc[2 * tj * nS + t];
        vR[t] = vsrc[2 * tj * nS + t];
    }
    __syncthreads();

    int ty = t >> 4, tx = t & 15;
    int a0 = ty * 6, b0 = tx * 6;

    unsigned long long acc2[6][3];
    #pragma unroll
    for (int ii = 0; ii < 6; ii++)
        #pragma unroll
        for (int jp = 0; jp < 3; jp++) acc2[ii][jp] = 0ULL;

    const float* Lbase = XL + a0 * PLD;
    const float* Rbase = XR + b0 * PLD;

    for (int k = 0; k < Dd; k += 4) {
        float4 l4[6], r4[6];
        #pragma unroll
        for (int ii = 0; ii < 6; ii++)
            l4[ii] = *(const float4*)(Lbase + ii * PLD + k);
        #pragma unroll
        for (int jj = 0; jj < 6; jj++)
            r4[jj] = *(const float4*)(Rbase + jj * PLD + k);
        const float* lf = (const float*)l4;
        const float* rf = (const float*)r4;
        #pragma unroll
        for (int e = 0; e < 4; e++) {
            unsigned long long r2[3];
            #pragma unroll
            for (int jp = 0; jp < 3; jp++)
                r2[jp] = pk2(rf[(2 * jp) * 4 + e], rf[(2 * jp + 1) * 4 + e]);
            #pragma unroll
            for (int ii = 0; ii < 6; ii++) {
                unsigned long long l2 = pk2(lf[ii * 4 + e], lf[ii * 4 + e]);
                #pragma unroll
                for (int jp = 0; jp < 3; jp++) fma2(acc2[ii][jp], l2, r2[jp]);
            }
        }
    }

    // ---- NTK epilogue + bilinear weights ----
    const float PI_F = 3.14159265358979323846f;
    float thc = acosf(0.9999f);
    float c1 = (0.9999f * (PI_F - thc) + sqrtf(1.f - 0.9999f * 0.9999f)) / PI_F;

    float partial = 0.f;
    #pragma unroll
    for (int ii = 0; ii < 6; ii++) {
        int a = a0 + ii;
        float da = dL[a], wa = vL[a];
        #pragma unroll
        for (int jp = 0; jp < 3; jp++) {
            float s0, s1;
            unpk2(s0, s1, acc2[ii][jp]);
            int b = b0 + 2 * jp;
            partial += wa * ntk_eval(s0, da, dR[b], c1) * vR[b];
            partial += wa * ntk_eval(s1, da, dR[b + 1], c1) * vR[b + 1];
        }
    }

    // ---- deterministic quadrant reduction (quadrant = graph pair) ----
    parr[t] = partial;
    __syncthreads();
    if (t < 4) {
        int qi = t >> 1, qj = t & 1;
        float s = 0.f;
        #pragma unroll 4
        for (int yy = qi * 8; yy < qi * 8 + 8; yy++)
            #pragma unroll
            for (int xx = qj * 8; xx < qj * 8 + 8; xx++)
                s += parr[yy * 16 + xx];
        int N = 2 * ti + qi, M = 2 * tj + qj;
        if (!isST) {
            KSS[N * Ng + M] = s;
            KSS[M * Ng + N] = s;
        } else {
            g_KST[N * Ng + M] = s;
        }
    }
}

// ============================================================
// Kernel C: regularize, Gauss-Jordan solve, pred (unchanged)
// ============================================================
__global__ void solve_kernel(const float* __restrict__ yS,
                             const float* __restrict__ KSS,
                             float* __restrict__ out) {
    __shared__ float aug[Ng][108];
    __shared__ float bv[128];
    __shared__ int bi[128];
    __shared__ float fct[Ng];
    int t = threadIdx.x;

    for (int idx = t; idx < Ng * Ng; idx += 128)
        aug[idx / Ng][idx % Ng] = KSS[idx];
    for (int idx = t; idx < Ng * Cc; idx += 128)
        aug[idx / Cc][Ng + idx % Cc] = yS[idx];
    __syncthreads();

    float tr = 0.f;
    for (int i = t; i < Ng; i += 128) tr += aug[i][i];
    bv[t] = tr;
    __syncthreads();
    for (int o = 64; o > 0; o >>= 1) {
        if (t < o) bv[t] += bv[t + o];
        __syncthreads();
    }
    float reg = 1e-6f * bv[0] / (float)Ng;
    __syncthreads();
    for (int i = t; i < Ng; i += 128) aug[i][i] += reg;
    __syncthreads();

    for (int k = 0; k < Ng; k++) {
        float best = -1.f;
        int bidx = k;
        for (int i = k + t; i < Ng; i += 128) {
            float a = fabsf(aug[i][k]);
            if (a > best) { best = a; bidx = i; }
        }
        bv[t] = best; bi[t] = bidx;
        __syncthreads();
        for (int o = 64; o > 0; o >>= 1) {
            if (t < o && bv[t + o] > bv[t]) { bv[t] = bv[t + o]; bi[t] = bi[t + o]; }
            __syncthreads();
        }
        int p = bi[0];
        if (p != k) {
            for (int j = t; j < 106; j += 128) {
                float tv = aug[k][j];
                aug[k][j] = aug[p][j];
                aug[p][j] = tv;
            }
        }
        __syncthreads();
        float piv = aug[k][k];
        for (int i = t; i < Ng; i += 128)
            fct[i] = (i == k) ? 0.f : (aug[i][k] / piv);
        __syncthreads();
        int ncol = 106 - k;
        for (int idx = t; idx < Ng * ncol; idx += 128) {
            int i = idx / ncol;
            if (i == k) continue;
            int j = k + (idx - i * ncol);
            aug[i][j] = fmaf(-fct[i], aug[k][j], aug[i][j]);
        }
        __syncthreads();
    }

    for (int idx = t; idx < Ng * Cc; idx += 128) {
        int i = idx / Cc, c = idx % Cc;
        aug[i][Ng + c] /= aug[i][i];
    }
    __syncthreads();

    for (int idx = t; idx < Ng * Cc; idx += 128) {
        int m = idx / Cc, c = idx % Cc;
        float acc = 0.f;
        for (int n2 = 0; n2 < Ng; n2++)
            acc += g_KST[n2 * Ng + m] * aug[n2][Ng + c];
        out[idx] = acc;
    }
}

// ============================================================
extern "C" void kernel_launch(void* const* d_in, const int* in_sizes, int n_in,
                              void* d_out, int out_size) {
    const float* U  = (const float*)d_in[0];
    const float* V  = (const float*)d_in[1];
    const float* XS = (const float*)d_in[2];
    const float* yS = (const float*)d_in[3];
    const float* AT = (const float*)d_in[4];
    const float* XT = (const float*)d_in[5];
    float* out = (float*)d_out;   // [pred (96,10) | K_SS (96,96)]
    float* KSS = out + Ng * Cc;

    precompute_kernel<<<Ng, 128>>>(U, V, XS, AT, XT);

    const int SMEM = (2 * TILE * PLD + 4 * TILE + 256) * (int)sizeof(float);
    cudaFuncSetAttribute(tile_kernel, cudaFuncAttributeMaxDynamicSharedMemorySize, SMEM);
    tile_kernel<<<NSS + NST, 256, SMEM>>>(XS, XT, KSS);

    solve_kernel<<<1, 128>>>(yS, KSS, out);
}

// round 4
// speedup vs baseline: 2.6460x; 2.6460x over previous
#include <cuda_runtime.h>
#include <cuda_bf16.h>
#include <math.h>
#include <stdint.h>

#define Ng 96
#define nS 48
#define RK 16
#define Dd 128
#define Cc 10
#define NSS 1176   // 48*49/2 graph-pair tiles (2x2 graphs per tile)
#define NST 2304   // 48*48
#define NTILES (NSS + NST)

// smem layout in u32 units: 4 matrices of 96 rows x 68 u32 (stride 68 => frag
// loads conflict-free: bank = (4g+tg) mod 32), then d/v vectors + warp slots.
#define LDU 68
#define AH_U 0
#define AL_U (96 * LDU)
#define BH_U (2 * 96 * LDU)
#define BL_U (3 * 96 * LDU)
#define DV_U (4 * 96 * LDU)          // dL[96] wL[96] dR[96] vR[96]
#define WS_U (DV_U + 384)            // 8 warp partial slots
#define SMEM_U32 (WS_U + 8)
#define SMEM_BYTES (SMEM_U32 * 4)

// ---------- persistent scratch ----------
__device__ float g_d0S[Ng * nS];
__device__ float g_d0T[Ng * nS];
__device__ float g_w[Ng * nS];
__device__ float g_z[Ng * nS];
__device__ float g_KST[Ng * Ng];
__device__ __nv_bfloat16 g_Shi[Ng * nS * Dd];
__device__ __nv_bfloat16 g_Slo[Ng * nS * Dd];
__device__ __nv_bfloat16 g_Thi[Ng * nS * Dd];
__device__ __nv_bfloat16 g_Tlo[Ng * nS * Dd];

// ---------- mma.sync m16n8k16 bf16 ----------
__device__ __forceinline__ void mma16816(float* c, uint32_t a0, uint32_t a1,
                                         uint32_t a2, uint32_t a3,
                                         uint32_t b0, uint32_t b1) {
    asm volatile(
        "mma.sync.aligned.m16n8k16.row.col.f32.bf16.bf16.f32 "
        "{%0,%1,%2,%3}, {%4,%5,%6,%7}, {%8,%9}, {%0,%1,%2,%3};"
        : "+f"(c[0]), "+f"(c[1]), "+f"(c[2]), "+f"(c[3])
        : "r"(a0), "r"(a1), "r"(a2), "r"(a3), "r"(b0), "r"(b1));
}

// ---------- NTK elementwise recursion ----------
__device__ __forceinline__ float ntk_eval(float dot, float da, float db, float c1) {
    const float PI_F = 3.14159265358979323846f;
    float p = da * db;
    float sigma = dot + 1e-4f;
    float ntk = sigma;
    float tmp = p + 1e-6f;
    #pragma unroll
    for (int l = 0; l < 2; l++) {
        float si = __fdividef(sigma, tmp);
        si = fminf(fmaxf(si, -0.9999f), 0.9999f);
        float th = acosf(si);
        float pit = PI_F - th;
        float s = (si * pit + sqrtf(fmaxf(1.f - si * si, 0.f))) * (1.f / PI_F);
        ntk = ntk * (pit * (1.f / PI_F)) + s;
        sigma = s * tmp;
        tmp = fmaf(c1, p, 1e-6f);
    }
    return ntk;
}

// ============================================================
// Kernel A: per-graph precompute + bf16 hi/lo split
// ============================================================
__global__ void precompute_kernel(const float* __restrict__ U,
                                  const float* __restrict__ V,
                                  const float* __restrict__ XS,
                                  const float* __restrict__ AT,
                                  const float* __restrict__ XT) {
    int g = blockIdx.x, t = threadIdx.x;
    const float* Ug = U + (size_t)g * nS * RK;
    const float* Vg = V + (size_t)g * RK * nS;
    const float* Ag = AT + (size_t)g * nS * nS;
    const float* xs = XS + (size_t)g * nS * Dd;
    const float* xt = XT + (size_t)g * nS * Dd;

    __shared__ float VU[RK][RK];
    __shared__ float u1[RK], u2a[RK], u2[RK], sv[nS];

    for (int idx = t; idx < nS * Dd; idx += 128) {
        float x = xs[idx];
        __nv_bfloat16 h = __float2bfloat16(x);
        g_Shi[(size_t)g * nS * Dd + idx] = h;
        g_Slo[(size_t)g * nS * Dd + idx] = __float2bfloat16(x - __bfloat162float(h));
        float y = xt[idx];
        __nv_bfloat16 h2 = __float2bfloat16(y);
        g_Thi[(size_t)g * nS * Dd + idx] = h2;
        g_Tlo[(size_t)g * nS * Dd + idx] = __float2bfloat16(y - __bfloat162float(h2));
    }

    if (t < nS) {
        const float4* row = (const float4*)(xs + t * Dd);
        float acc = 0.f;
        #pragma unroll
        for (int k = 0; k < Dd / 4; k++) {
            float4 v = row[k];
            acc += v.x * v.x + v.y * v.y + v.z * v.z + v.w * v.w;
        }
        g_d0S[g * nS + t] = sqrtf(acc + 1e-4f);
    } else if (t < 2 * nS) {
        int r = t - nS;
        const float4* row = (const float4*)(xt + r * Dd);
        float acc = 0.f;
        #pragma unroll
        for (int k = 0; k < Dd / 4; k++) {
            float4 v = row[k];
            acc += v.x * v.x + v.y * v.y + v.z * v.z + v.w * v.w;
        }
        g_d0T[g * nS + r] = sqrtf(acc + 1e-4f);
    }

    for (int e = t; e < RK * RK; e += blockDim.x) {
        int i = e / RK, j = e % RK;
        float acc = 0.f;
        for (int a = 0; a < nS; a++) acc += Vg[i * nS + a] * Ug[a * RK + j];
        VU[i][j] = acc;
    }
    __syncthreads();

    if (t < RK) {
        float acc = 0.f;
        for (int a = 0; a < nS; a++) acc += Ug[a * RK + t];
        u1[t] = acc;
    } else if (t < RK + nS) {
        int i = t - RK;
        float acc = 0.f;
        for (int j = 0; j < nS; j++) acc += Ag[j * nS + i];
        sv[i] = acc + 1e-4f;
    }
    __syncthreads();
    if (t < RK) {
        float acc = 0.f;
        for (int r = 0; r < RK; r++) acc += VU[r][t] * u1[r];
        u2a[t] = acc;
    }
    __syncthreads();
    if (t < RK) {
        float acc = 0.f;
        for (int r = 0; r < RK; r++) acc += VU[r][t] * u2a[r];
        u2[t] = acc;
    }
    __syncthreads();
    if (t < nS) {
        float acc = 0.f;
        for (int r = 0; r < RK; r++) acc += Vg[r * nS + t] * u2[r];
        g_w[g * nS + t] = acc;
    } else if (t < 2 * nS) {
        int i = t - nS;
        float acc = 0.f;
        for (int j = 0; j < nS; j++) acc += Ag[j * nS + i] * sv[j];
        g_z[g * nS + i] = acc + 1e-4f * sv[i];
    }
}

// ============================================================
// Kernel B: HMMA (mma.sync) tile kernel. 96x96 sigma tile per
// block via 3-split bf16 mma, fused NTK epilogue in registers.
// ============================================================
__global__ void __launch_bounds__(256, 2)
mma_tile_kernel(float* __restrict__ KSS) {
    int bid = blockIdx.x;
    int ti, tj, isST;
    if (bid < NSS) {
        isST = 0;
        int rem = bid, cnt = 48;
        ti = 0;
        while (rem >= cnt) { rem -= cnt; ti++; cnt--; }
        tj = ti + rem;
    } else {
        isST = 1;
        int r = bid - NSS;
        ti = r / 48;
        tj = r - ti * 48;
    }

    extern __shared__ uint32_t smU[];
    int t = threadIdx.x;
    int w = t >> 5, lane = t & 31;
    int g2 = lane >> 2, tg = lane & 3;

    const uint4* ShiV = (const uint4*)g_Shi;
    const uint4* SloV = (const uint4*)g_Slo;
    const uint4* RhiV = isST ? (const uint4*)g_Thi : ShiV;
    const uint4* RloV = isST ? (const uint4*)g_Tlo : SloV;
    int rowL = ti * 96, rowR = tj * 96;

    // ---- load 4 tiles (96 x 64 u32 each) via uint4 ----
    for (int idx = t; idx < 96 * 16; idx += 256) {
        int r = idx >> 4, c4 = idx & 15;
        int so = r * LDU + c4 * 4;
        *(uint4*)(smU + AH_U + so) = ShiV[(size_t)(rowL + r) * 16 + c4];
        *(uint4*)(smU + AL_U + so) = SloV[(size_t)(rowL + r) * 16 + c4];
        *(uint4*)(smU + BH_U + so) = RhiV[(size_t)(rowR + r) * 16 + c4];
        *(uint4*)(smU + BL_U + so) = RloV[(size_t)(rowR + r) * 16 + c4];
    }
    // ---- d/v vectors ----
    float* dv = (float*)(smU + DV_U);
    for (int idx = t; idx < 384; idx += 256) {
        float v;
        if (idx < 96)        v = g_d0S[rowL + idx];
        else if (idx < 192)  v = g_w[rowL + idx - 96];
        else if (idx < 288)  v = (isST ? g_d0T : g_d0S)[rowR + idx - 192];
        else                 v = (isST ? g_z : g_w)[rowR + idx - 288];
        dv[idx] = v;
    }
    __syncthreads();

    // ---- mainloop: warp (wr, wc) owns rows [wr*48,+48), cols [wc*24,+24) ----
    int wr = w >> 2, wc = w & 3;
    int mrow0 = wr * 48, ncol0 = wc * 24;

    float acc[3][3][4];
    #pragma unroll
    for (int mi = 0; mi < 3; mi++)
        #pragma unroll
        for (int nj = 0; nj < 3; nj++)
            #pragma unroll
            for (int e = 0; e < 4; e++) acc[mi][nj][e] = 0.f;

    #pragma unroll
    for (int s = 0; s < 3; s++) {
        const uint32_t* A = smU + (s == 2 ? AL_U : AH_U);
        const uint32_t* B = smU + (s == 1 ? BL_U : BH_U);
        #pragma unroll
        for (int ks = 0; ks < 8; ks++) {
            int col = ks * 8 + tg;
            uint32_t b0[3], b1[3];
            #pragma unroll
            for (int nj = 0; nj < 3; nj++) {
                int rb = ncol0 + nj * 8 + g2;
                b0[nj] = B[rb * LDU + col];
                b1[nj] = B[rb * LDU + col + 4];
            }
            #pragma unroll
            for (int mi = 0; mi < 3; mi++) {
                int ra = mrow0 + mi * 16 + g2;
                uint32_t a0 = A[ra * LDU + col];
                uint32_t a1 = A[(ra + 8) * LDU + col];
                uint32_t a2 = A[ra * LDU + col + 4];
                uint32_t a3 = A[(ra + 8) * LDU + col + 4];
                #pragma unroll
                for (int nj = 0; nj < 3; nj++)
                    mma16816(acc[mi][nj], a0, a1, a2, a3, b0[nj], b1[nj]);
            }
        }
    }

    // ---- fused NTK epilogue on register fragments ----
    const float PI_F = 3.14159265358979323846f;
    float thc = acosf(0.9999f);
    float c1 = (0.9999f * (PI_F - thc) + sqrtf(1.f - 0.9999f * 0.9999f)) / PI_F;

    const float* dL = dv;
    const float* wL = dv + 96;
    const float* dR = dv + 192;
    const float* vR = dv + 288;

    float partial = 0.f;
    #pragma unroll
    for (int mi = 0; mi < 3; mi++) {
        int r0 = mrow0 + mi * 16 + g2, r1 = r0 + 8;
        float da0 = dL[r0], wa0 = wL[r0];
        float da1 = dL[r1], wa1 = wL[r1];
        #pragma unroll
        for (int nj = 0; nj < 3; nj++) {
            int c0 = ncol0 + nj * 8 + tg * 2, c1i = c0 + 1;
            float db0 = dR[c0], vb0 = vR[c0];
            float db1 = dR[c1i], vb1 = vR[c1i];
            partial += wa0 * ntk_eval(acc[mi][nj][0], da0, db0, c1) * vb0;
            partial += wa0 * ntk_eval(acc[mi][nj][1], da0, db1, c1) * vb1;
            partial += wa1 * ntk_eval(acc[mi][nj][2], da1, db0, c1) * vb0;
            partial += wa1 * ntk_eval(acc[mi][nj][3], da1, db1, c1) * vb1;
        }
    }

    // ---- warp reduce (deterministic tree) + quadrant combine ----
    #pragma unroll
    for (int o = 16; o > 0; o >>= 1)
        partial += __shfl_down_sync(0xffffffffu, partial, o);
    float* wslot = (float*)(smU + WS_U);
    if (lane == 0) wslot[w] = partial;
    __syncthreads();

    if (t < 4) {
        int qi = t >> 1, qj = t & 1;
        int w0 = qi * 4 + qj * 2;
        float s = wslot[w0] + wslot[w0 + 1];
        int N = 2 * ti + qi, M = 2 * tj + qj;
        if (!isST) {
            if (!(ti == tj && qi > qj)) {
                KSS[N * Ng + M] = s;
                KSS[M * Ng + N] = s;
            }
        } else {
            g_KST[N * Ng + M] = s;
        }
    }
}

// ============================================================
// Kernel C: no-pivot Gauss-Jordan (SPD) + pred, 512 threads
// ============================================================
__global__ void solve_kernel(const float* __restrict__ yS,
                             const float* __restrict__ KSS,
                             float* __restrict__ out) {
    __shared__ float aug[96][128];
    __shared__ float fct[96];
    __shared__ float rtr;
    int t = threadIdx.x;
    int j = t & 127, i0 = t >> 7;

    for (int i = i0; i < 96; i += 4) {
        float v = 0.f;
        if (j < 96) v = KSS[i * 96 + j];
        else if (j < 106) v = yS[i * 10 + (j - 96)];
        aug[i][j] = v;
    }
    __syncthreads();

    if (t < 32) {
        float tr = 0.f;
        for (int i = t; i < 96; i += 32) tr += aug[i][i];
        #pragma unroll
        for (int o = 16; o > 0; o >>= 1) tr += __shfl_down_sync(0xffffffffu, tr, o);
        if (t == 0) rtr = 1e-6f * tr / 96.f;
    }
    __syncthreads();
    if (t < 96) aug[t][t] += rtr;
    __syncthreads();

    for (int k = 0; k < 96; k++) {
        if (t < 96) {
            float piv = aug[k][k];
            fct[t] = (t == k) ? 0.f : aug[t][k] / piv;
        }
        __syncthreads();
        if (j > k && j < 106) {
            float pk = aug[k][j];
            #pragma unroll 4
            for (int i = i0; i < 96; i += 4)
                aug[i][j] -= fct[i] * pk;
        }
        __syncthreads();
    }

    for (int idx = t; idx < 960; idx += 512) {
        int i = idx / 10, c = idx - i * 10;
        aug[i][96 + c] /= aug[i][i];
    }
    __syncthreads();

    for (int idx = t; idx < 960; idx += 512) {
        int m = idx / 10, c = idx - m * 10;
        float acc = 0.f;
        for (int n2 = 0; n2 < 96; n2++)
            acc += g_KST[n2 * 96 + m] * aug[n2][96 + c];
        out[idx] = acc;
    }
}

// ============================================================
extern "C" void kernel_launch(void* const* d_in, const int* in_sizes, int n_in,
                              void* d_out, int out_size) {
    const float* U  = (const float*)d_in[0];
    const float* V  = (const float*)d_in[1];
    const float* XS = (const float*)d_in[2];
    const float* yS = (const float*)d_in[3];
    const float* AT = (const float*)d_in[4];
    const float* XT = (const float*)d_in[5];
    float* out = (float*)d_out;   // [pred (96,10) | K_SS (96,96)]
    float* KSS = out + Ng * Cc;

    precompute_kernel<<<Ng, 128>>>(U, V, XS, AT, XT);

    cudaFuncSetAttribute(mma_tile_kernel, cudaFuncAttributeMaxDynamicSharedMemorySize,
                         SMEM_BYTES);
    mma_tile_kernel<<<NTILES, 256, SMEM_BYTES>>>(KSS);

    solve_kernel<<<1, 512>>>(yS, KSS, out);
}

// round 5
// speedup vs baseline: 2.6814x; 1.0134x over previous
#include <cuda_runtime.h>
#include <cuda_bf16.h>
#include <math.h>
#include <stdint.h>

#define Ng 96
#define nS 48
#define RK 16
#define Dd 128
#define Cc 10
#define NSS 1176   // 48*49/2 graph-pair tiles (2x2 graphs per tile)
#define NST 2304   // 48*48
#define NTILES (NSS + NST)

// smem layout in u32 units: 4 matrices of 96 rows x 68 u32 (stride 68 => ldmatrix
// row addresses conflict-free: bank start = 4r mod 32), then d/v vectors + slots.
#define LDU 68
#define LDB 272                      // row stride bytes
#define AH_U 0
#define AL_U (96 * LDU)
#define BH_U (2 * 96 * LDU)
#define BL_U (3 * 96 * LDU)
#define DV_U (4 * 96 * LDU)          // dL[96] wL[96] dR[96] vR[96]
#define WS_U (DV_U + 384)            // 8 warp partial slots
#define SMEM_U32 (WS_U + 8)
#define SMEM_BYTES (SMEM_U32 * 4)

// ---------- persistent scratch ----------
__device__ float g_d0S[Ng * nS];
__device__ float g_d0T[Ng * nS];
__device__ float g_w[Ng * nS];
__device__ float g_z[Ng * nS];
__device__ float g_KST[Ng * Ng];
__device__ __nv_bfloat16 g_Shi[Ng * nS * Dd];
__device__ __nv_bfloat16 g_Slo[Ng * nS * Dd];
__device__ __nv_bfloat16 g_Thi[Ng * nS * Dd];
__device__ __nv_bfloat16 g_Tlo[Ng * nS * Dd];

// ---------- mma.sync m16n8k16 bf16 ----------
__device__ __forceinline__ void mma16816(float* c, uint32_t a0, uint32_t a1,
                                         uint32_t a2, uint32_t a3,
                                         uint32_t b0, uint32_t b1) {
    asm volatile(
        "mma.sync.aligned.m16n8k16.row.col.f32.bf16.bf16.f32 "
        "{%0,%1,%2,%3}, {%4,%5,%6,%7}, {%8,%9}, {%0,%1,%2,%3};"
        : "+f"(c[0]), "+f"(c[1]), "+f"(c[2]), "+f"(c[3])
        : "r"(a0), "r"(a1), "r"(a2), "r"(a3), "r"(b0), "r"(b1));
}
__device__ __forceinline__ void ldmx4(uint32_t* r, uint32_t addr) {
    asm volatile("ldmatrix.sync.aligned.m8n8.x4.shared.b16 {%0,%1,%2,%3}, [%4];"
                 : "=r"(r[0]), "=r"(r[1]), "=r"(r[2]), "=r"(r[3]) : "r"(addr));
}
__device__ __forceinline__ void ldmx2(uint32_t* r, uint32_t addr) {
    asm volatile("ldmatrix.sync.aligned.m8n8.x2.shared.b16 {%0,%1}, [%2];"
                 : "=r"(r[0]), "=r"(r[1]) : "r"(addr));
}
__device__ __forceinline__ uint32_t smem_u32(const void* p) {
    uint32_t a;
    asm("{ .reg .u64 t; cvta.to.shared.u64 t, %1; cvt.u32.u64 %0, t; }"
        : "=r"(a) : "l"(p));
    return a;
}

// ---------- NTK elementwise recursion ----------
__device__ __forceinline__ float ntk_eval(float dot, float da, float db, float c1) {
    const float PI_F = 3.14159265358979323846f;
    float p = da * db;
    float sigma = dot + 1e-4f;
    float ntk = sigma;
    float tmp = p + 1e-6f;
    #pragma unroll
    for (int l = 0; l < 2; l++) {
        float si = __fdividef(sigma, tmp);
        si = fminf(fmaxf(si, -0.9999f), 0.9999f);
        float th = acosf(si);
        float pit = PI_F - th;
        float s = (si * pit + sqrtf(fmaxf(1.f - si * si, 0.f))) * (1.f / PI_F);
        ntk = ntk * (pit * (1.f / PI_F)) + s;
        sigma = s * tmp;
        tmp = fmaf(c1, p, 1e-6f);
    }
    return ntk;
}

// ============================================================
// Kernel A0: wide bf16 hi/lo split (memory-bound)
// ============================================================
__global__ void split_kernel(const float* __restrict__ XS,
                             const float* __restrict__ XT) {
    int idx = blockIdx.x * blockDim.x + threadIdx.x;  // over float4s
    const int n4 = Ng * nS * Dd / 4;                  // 147456
    if (idx >= n4) return;
    float4 a = ((const float4*)XS)[idx];
    float4 b = ((const float4*)XT)[idx];
    __nv_bfloat16 h;
    __nv_bfloat16 sh[4], sl[4], th[4], tl[4];
    const float* af = (const float*)&a;
    const float* bf = (const float*)&b;
    #pragma unroll
    for (int e = 0; e < 4; e++) {
        h = __float2bfloat16(af[e]);
        sh[e] = h; sl[e] = __float2bfloat16(af[e] - __bfloat162float(h));
        h = __float2bfloat16(bf[e]);
        th[e] = h; tl[e] = __float2bfloat16(bf[e] - __bfloat162float(h));
    }
    ((uint2*)g_Shi)[idx] = *(uint2*)sh;
    ((uint2*)g_Slo)[idx] = *(uint2*)sl;
    ((uint2*)g_Thi)[idx] = *(uint2*)th;
    ((uint2*)g_Tlo)[idx] = *(uint2*)tl;
}

// ============================================================
// Kernel A1: per-graph precompute (d0, w, z)
// ============================================================
__global__ void precompute_kernel(const float* __restrict__ U,
                                  const float* __restrict__ V,
                                  const float* __restrict__ XS,
                                  const float* __restrict__ AT,
                                  const float* __restrict__ XT) {
    int g = blockIdx.x, t = threadIdx.x;
    const float* Ug = U + (size_t)g * nS * RK;
    const float* Vg = V + (size_t)g * RK * nS;
    const float* Ag = AT + (size_t)g * nS * nS;
    const float* xs = XS + (size_t)g * nS * Dd;
    const float* xt = XT + (size_t)g * nS * Dd;

    __shared__ float VU[RK][RK];
    __shared__ float u1[RK], u2a[RK], u2[RK], sv[nS];

    if (t < nS) {
        const float4* row = (const float4*)(xs + t * Dd);
        float acc = 0.f;
        #pragma unroll
        for (int k = 0; k < Dd / 4; k++) {
            float4 v = row[k];
            acc += v.x * v.x + v.y * v.y + v.z * v.z + v.w * v.w;
        }
        g_d0S[g * nS + t] = sqrtf(acc + 1e-4f);
    } else if (t < 2 * nS) {
        int r = t - nS;
        const float4* row = (const float4*)(xt + r * Dd);
        float acc = 0.f;
        #pragma unroll
        for (int k = 0; k < Dd / 4; k++) {
            float4 v = row[k];
            acc += v.x * v.x + v.y * v.y + v.z * v.z + v.w * v.w;
        }
        g_d0T[g * nS + r] = sqrtf(acc + 1e-4f);
    }

    for (int e = t; e < RK * RK; e += blockDim.x) {
        int i = e / RK, j = e % RK;
        float acc = 0.f;
        for (int a = 0; a < nS; a++) acc += Vg[i * nS + a] * Ug[a * RK + j];
        VU[i][j] = acc;
    }
    __syncthreads();

    if (t < RK) {
        float acc = 0.f;
        for (int a = 0; a < nS; a++) acc += Ug[a * RK + t];
        u1[t] = acc;
    } else if (t < RK + nS) {
        int i = t - RK;
        float acc = 0.f;
        for (int j = 0; j < nS; j++) acc += Ag[j * nS + i];
        sv[i] = acc + 1e-4f;
    }
    __syncthreads();
    if (t < RK) {
        float acc = 0.f;
        for (int r = 0; r < RK; r++) acc += VU[r][t] * u1[r];
        u2a[t] = acc;
    }
    __syncthreads();
    if (t < RK) {
        float acc = 0.f;
        for (int r = 0; r < RK; r++) acc += VU[r][t] * u2a[r];
        u2[t] = acc;
    }
    __syncthreads();
    if (t < nS) {
        float acc = 0.f;
        for (int r = 0; r < RK; r++) acc += Vg[r * nS + t] * u2[r];
        g_w[g * nS + t] = acc;
    } else if (t < 2 * nS) {
        int i = t - nS;
        float acc = 0.f;
        for (int j = 0; j < nS; j++) acc += Ag[j * nS + i] * sv[j];
        g_z[g * nS + i] = acc + 1e-4f * sv[i];
    }
}

// ============================================================
// Kernel B: HMMA tile kernel with ldmatrix fragment loads.
// ============================================================
__global__ void __launch_bounds__(256, 2)
mma_tile_kernel(float* __restrict__ KSS) {
    int bid = blockIdx.x;
    int ti, tj, isST;
    if (bid < NSS) {
        isST = 0;
        int rem = bid, cnt = 48;
        ti = 0;
        while (rem >= cnt) { rem -= cnt; ti++; cnt--; }
        tj = ti + rem;
    } else {
        isST = 1;
        int r = bid - NSS;
        ti = r / 48;
        tj = r - ti * 48;
    }

    extern __shared__ uint32_t smU[];
    uint32_t sbase = smem_u32(smU);
    int t = threadIdx.x;
    int w = t >> 5, lane = t & 31;
    int g2 = lane >> 2, tg = lane & 3;

    const uint4* ShiV = (const uint4*)g_Shi;
    const uint4* SloV = (const uint4*)g_Slo;
    const uint4* RhiV = isST ? (const uint4*)g_Thi : ShiV;
    const uint4* RloV = isST ? (const uint4*)g_Tlo : SloV;
    int rowL = ti * 96, rowR = tj * 96;

    // ---- load 4 tiles (96 rows x 64 u32) via uint4 ----
    for (int idx = t; idx < 96 * 16; idx += 256) {
        int r = idx >> 4, c4 = idx & 15;
        int so = r * LDU + c4 * 4;
        *(uint4*)(smU + AH_U + so) = ShiV[(size_t)(rowL + r) * 16 + c4];
        *(uint4*)(smU + AL_U + so) = SloV[(size_t)(rowL + r) * 16 + c4];
        *(uint4*)(smU + BH_U + so) = RhiV[(size_t)(rowR + r) * 16 + c4];
        *(uint4*)(smU + BL_U + so) = RloV[(size_t)(rowR + r) * 16 + c4];
    }
    // ---- d/v vectors ----
    float* dv = (float*)(smU + DV_U);
    for (int idx = t; idx < 384; idx += 256) {
        float v;
        if (idx < 96)        v = g_d0S[rowL + idx];
        else if (idx < 192)  v = g_w[rowL + idx - 96];
        else if (idx < 288)  v = (isST ? g_d0T : g_d0S)[rowR + idx - 192];
        else                 v = (isST ? g_z : g_w)[rowR + idx - 288];
        dv[idx] = v;
    }
    __syncthreads();

    // ---- warp (wr, wc): rows [wr*48,+48), cols [wc*24,+24) ----
    int wr = w >> 2, wc = w & 3;
    int mrow0 = wr * 48, ncol0 = wc * 24;

    // per-lane ldmatrix base offsets (bytes within a matrix)
    int l7 = lane & 7;
    uint32_t aoff = (uint32_t)((mrow0 + l7 + ((lane >> 3) & 1) * 8) * LDB +
                               ((lane >> 4) & 1) * 16);
    uint32_t boff01 = (uint32_t)((ncol0 + ((lane >> 4) & 1) * 8 + l7) * LDB +
                                 ((lane >> 3) & 1) * 16);
    uint32_t boff2 = (uint32_t)((ncol0 + 16 + l7) * LDB +
                                ((lane >> 3) & 1) * 16);

    float acc[3][3][4];
    #pragma unroll
    for (int mi = 0; mi < 3; mi++)
        #pragma unroll
        for (int nj = 0; nj < 3; nj++)
            #pragma unroll
            for (int e = 0; e < 4; e++) acc[mi][nj][e] = 0.f;

    #pragma unroll
    for (int s = 0; s < 3; s++) {
        uint32_t Ab = sbase + (uint32_t)((s == 2 ? AL_U : AH_U) * 4);
        uint32_t Bb = sbase + (uint32_t)((s == 1 ? BL_U : BH_U) * 4);
        #pragma unroll
        for (int ks = 0; ks < 8; ks++) {
            uint32_t kb = (uint32_t)(ks * 32);
            uint32_t b01[4], b2[2];
            ldmx4(b01, Bb + boff01 + kb);
            ldmx2(b2, Bb + boff2 + kb);
            #pragma unroll
            for (int mi = 0; mi < 3; mi++) {
                uint32_t a[4];
                ldmx4(a, Ab + aoff + (uint32_t)(mi * 16 * LDB) + kb);
                mma16816(acc[mi][0], a[0], a[1], a[2], a[3], b01[0], b01[1]);
                mma16816(acc[mi][1], a[0], a[1], a[2], a[3], b01[2], b01[3]);
                mma16816(acc[mi][2], a[0], a[1], a[2], a[3], b2[0], b2[1]);
            }
        }
    }

    // ---- fused NTK epilogue on register fragments ----
    const float PI_F = 3.14159265358979323846f;
    float thc = acosf(0.9999f);
    float c1 = (0.9999f * (PI_F - thc) + sqrtf(1.f - 0.9999f * 0.9999f)) / PI_F;

    const float* dL = dv;
    const float* wL = dv + 96;
    const float* dR = dv + 192;
    const float* vR = dv + 288;

    float partial = 0.f;
    #pragma unroll
    for (int mi = 0; mi < 3; mi++) {
        int r0 = mrow0 + mi * 16 + g2, r1 = r0 + 8;
        float da0 = dL[r0], wa0 = wL[r0];
        float da1 = dL[r1], wa1 = wL[r1];
        #pragma unroll
        for (int nj = 0; nj < 3; nj++) {
            int c0 = ncol0 + nj * 8 + tg * 2, c1i = c0 + 1;
            float db0 = dR[c0], vb0 = vR[c0];
            float db1 = dR[c1i], vb1 = vR[c1i];
            partial += wa0 * ntk_eval(acc[mi][nj][0], da0, db0, c1) * vb0;
            partial += wa0 * ntk_eval(acc[mi][nj][1], da0, db1, c1) * vb1;
            partial += wa1 * ntk_eval(acc[mi][nj][2], da1, db0, c1) * vb0;
            partial += wa1 * ntk_eval(acc[mi][nj][3], da1, db1, c1) * vb1;
        }
    }

    // ---- warp reduce + quadrant combine ----
    #pragma unroll
    for (int o = 16; o > 0; o >>= 1)
        partial += __shfl_down_sync(0xffffffffu, partial, o);
    float* wslot = (float*)(smU + WS_U);
    if (lane == 0) wslot[w] = partial;
    __syncthreads();

    if (t < 4) {
        int qi = t >> 1, qj = t & 1;
        int w0 = qi * 4 + qj * 2;
        float s = wslot[w0] + wslot[w0 + 1];
        int N = 2 * ti + qi, M = 2 * tj + qj;
        if (!isST) {
            if (!(ti == tj && qi > qj)) {
                KSS[N * Ng + M] = s;
                KSS[M * Ng + N] = s;
            }
        } else {
            g_KST[N * Ng + M] = s;
        }
    }
}

// ============================================================
// Kernel C: no-pivot Gauss-Jordan (SPD) + pred, 512 threads
// ============================================================
__global__ void solve_kernel(const float* __restrict__ yS,
                             const float* __restrict__ KSS,
                             float* __restrict__ out) {
    __shared__ float aug[96][128];
    __shared__ float fct[96];
    __shared__ float rtr;
    int t = threadIdx.x;
    int j = t & 127, i0 = t >> 7;

    for (int i = i0; i < 96; i += 4) {
        float v = 0.f;
        if (j < 96) v = KSS[i * 96 + j];
        else if (j < 106) v = yS[i * 10 + (j - 96)];
        aug[i][j] = v;
    }
    __syncthreads();

    if (t < 32) {
        float tr = 0.f;
        for (int i = t; i < 96; i += 32) tr += aug[i][i];
        #pragma unroll
        for (int o = 16; o > 0; o >>= 1) tr += __shfl_down_sync(0xffffffffu, tr, o);
        if (t == 0) rtr = 1e-6f * tr / 96.f;
    }
    __syncthreads();
    if (t < 96) aug[t][t] += rtr;
    __syncthreads();

    for (int k = 0; k < 96; k++) {
        if (t < 96) {
            float piv = aug[k][k];
            fct[t] = (t == k) ? 0.f : aug[t][k] / piv;
        }
        __syncthreads();
        if (j > k && j < 106) {
            float pk = aug[k][j];
            #pragma unroll 4
            for (int i = i0; i < 96; i += 4)
                aug[i][j] -= fct[i] * pk;
        }
        __syncthreads();
    }

    for (int idx = t; idx < 960; idx += 512) {
        int i = idx / 10, c = idx - i * 10;
        aug[i][96 + c] /= aug[i][i];
    }
    __syncthreads();

    for (int idx = t; idx < 960; idx += 512) {
        int m = idx / 10, c = idx - m * 10;
        float acc = 0.f;
        for (int n2 = 0; n2 < 96; n2++)
            acc += g_KST[n2 * 96 + m] * aug[n2][96 + c];
        out[idx] = acc;
    }
}

// ============================================================
extern "C" void kernel_launch(void* const* d_in, const int* in_sizes, int n_in,
                              void* d_out, int out_size) {
    const float* U  = (const float*)d_in[0];
    const float* V  = (const float*)d_in[1];
    const float* XS = (const float*)d_in[2];
    const float* yS = (const float*)d_in[3];
    const float* AT = (const float*)d_in[4];
    const float* XT = (const float*)d_in[5];
    float* out = (float*)d_out;   // [pred (96,10) | K_SS (96,96)]
    float* KSS = out + Ng * Cc;

    split_kernel<<<(Ng * nS * Dd / 4 + 255) / 256, 256>>>(XS, XT);
    precompute_kernel<<<Ng, 128>>>(U, V, XS, AT, XT);

    cudaFuncSetAttribute(mma_tile_kernel, cudaFuncAttributeMaxDynamicSharedMemorySize,
                         SMEM_BYTES);
    mma_tile_kernel<<<NTILES, 256, SMEM_BYTES>>>(KSS);

    solve_kernel<<<1, 512>>>(yS, KSS, out);
}

// round 6
// speedup vs baseline: 2.8216x; 1.0523x over previous
#include <cuda_runtime.h>
#include <cuda_bf16.h>
#include <math.h>
#include <stdint.h>

#define Ng 96
#define nS 48
#define RK 16
#define Dd 128
#define Cc 10
#define NSS 1176   // 48*49/2 graph-pair tiles (2x2 graphs per tile)
#define NST 2304   // 48*48
#define NTILES (NSS + NST)

// smem layout in u32 units: 4 matrices of 96 rows x 68 u32 (stride 68 => ldmatrix
// row addresses conflict-free), then d/v vectors + warp slots.
#define LDU 68
#define LDB 272                      // row stride bytes
#define AH_U 0
#define AL_U (96 * LDU)
#define BH_U (2 * 96 * LDU)
#define BL_U (3 * 96 * LDU)
#define DV_U (4 * 96 * LDU)          // dL[96] wL[96] dR[96] vR[96]
#define WS_U (DV_U + 384)            // 8 warp partial slots
#define SMEM_U32 (WS_U + 8)
#define SMEM_BYTES (SMEM_U32 * 4)

// ---------- persistent scratch ----------
__device__ float g_d0S[Ng * nS];
__device__ float g_d0T[Ng * nS];
__device__ float g_w[Ng * nS];
__device__ float g_z[Ng * nS];
__device__ float g_KST[Ng * Ng];
__device__ __nv_bfloat16 g_Shi[Ng * nS * Dd];
__device__ __nv_bfloat16 g_Slo[Ng * nS * Dd];
__device__ __nv_bfloat16 g_Thi[Ng * nS * Dd];
__device__ __nv_bfloat16 g_Tlo[Ng * nS * Dd];

// ---------- mma.sync m16n8k16 bf16 ----------
__device__ __forceinline__ void mma16816(float* c, uint32_t a0, uint32_t a1,
                                         uint32_t a2, uint32_t a3,
                                         uint32_t b0, uint32_t b1) {
    asm volatile(
        "mma.sync.aligned.m16n8k16.row.col.f32.bf16.bf16.f32 "
        "{%0,%1,%2,%3}, {%4,%5,%6,%7}, {%8,%9}, {%0,%1,%2,%3};"
        : "+f"(c[0]), "+f"(c[1]), "+f"(c[2]), "+f"(c[3])
        : "r"(a0), "r"(a1), "r"(a2), "r"(a3), "r"(b0), "r"(b1));
}
__device__ __forceinline__ void ldmx4(uint32_t* r, uint32_t addr) {
    asm volatile("ldmatrix.sync.aligned.m8n8.x4.shared.b16 {%0,%1,%2,%3}, [%4];"
                 : "=r"(r[0]), "=r"(r[1]), "=r"(r[2]), "=r"(r[3]) : "r"(addr));
}
__device__ __forceinline__ void ldmx2(uint32_t* r, uint32_t addr) {
    asm volatile("ldmatrix.sync.aligned.m8n8.x2.shared.b16 {%0,%1}, [%2];"
                 : "=r"(r[0]), "=r"(r[1]) : "r"(addr));
}
__device__ __forceinline__ uint32_t smem_u32(const void* p) {
    uint32_t a;
    asm("{ .reg .u64 t; cvta.to.shared.u64 t, %1; cvt.u32.u64 %0, t; }"
        : "=r"(a) : "l"(p));
    return a;
}

// ---------- fast NTK recursion (custom acos poly, A&S 4.4.46) ----------
__device__ __forceinline__ float acos_pos(float ax, float u) {
    // acos(ax) for ax in [0,1]; u = sqrt(1-ax). |err| <= ~7e-8.
    float p = fmaf(ax, -0.0012624911f, 0.0066700901f);
    p = fmaf(ax, p, -0.0170881256f);
    p = fmaf(ax, p, 0.0308918810f);
    p = fmaf(ax, p, -0.0501743046f);
    p = fmaf(ax, p, 0.0889789874f);
    p = fmaf(ax, p, -0.2145988016f);
    p = fmaf(ax, p, 1.5707963050f);
    return u * p;
}

__device__ __forceinline__ float ntk_eval(float dot, float da, float db, float ic1) {
    const float PI_F = 3.14159265358979323846f;
    const float IPI = 0.318309886183790672f;
    float pw = da * db;
    float sigma = dot + 1e-4f;
    float tmp = pw + 1e-6f;
    // ---- layer 1 ----
    float si = __fdividef(sigma, tmp);
    si = fminf(fmaxf(si, -0.9999f), 0.9999f);
    float ax = fabsf(si);
    float u = sqrtf(1.f - ax);
    float v = sqrtf(1.f + ax);
    float thp = acos_pos(ax, u);
    float th = (si < 0.f) ? (PI_F - thp) : thp;
    float pit = PI_F - th;
    float root = u * v;                       // sqrt(1 - si^2)
    float s = fmaf(si, pit, root) * IPI;
    float ntk = fmaf(sigma, pit * IPI, s);
    // ---- layer 2: si2 = s*tmp1/tmp2 = s/c1 (1e-6 terms negligible: p ~ 1e2) ----
    float si2 = fminf(s * ic1, 0.9999f);      // s >= 0 always
    float u2 = sqrtf(1.f - si2);
    float v2 = sqrtf(1.f + si2);
    float pit2 = PI_F - acos_pos(si2, u2);
    float s2 = fmaf(si2, pit2, u2 * v2) * IPI;
    return fmaf(ntk, pit2 * IPI, s2);
}

// ============================================================
// Kernel A0: wide bf16 hi/lo split (memory-bound)
// ============================================================
__global__ void split_kernel(const float* __restrict__ XS,
                             const float* __restrict__ XT) {
    int idx = blockIdx.x * blockDim.x + threadIdx.x;  // over float4s
    const int n4 = Ng * nS * Dd / 4;
    if (idx >= n4) return;
    float4 a = ((const float4*)XS)[idx];
    float4 b = ((const float4*)XT)[idx];
    __nv_bfloat16 h;
    __nv_bfloat16 sh[4], sl[4], th[4], tl[4];
    const float* af = (const float*)&a;
    const float* bf = (const float*)&b;
    #pragma unroll
    for (int e = 0; e < 4; e++) {
        h = __float2bfloat16(af[e]);
        sh[e] = h; sl[e] = __float2bfloat16(af[e] - __bfloat162float(h));
        h = __float2bfloat16(bf[e]);
        th[e] = h; tl[e] = __float2bfloat16(bf[e] - __bfloat162float(h));
    }
    ((uint2*)g_Shi)[idx] = *(uint2*)sh;
    ((uint2*)g_Slo)[idx] = *(uint2*)sl;
    ((uint2*)g_Thi)[idx] = *(uint2*)th;
    ((uint2*)g_Tlo)[idx] = *(uint2*)tl;
}

// ============================================================
// Kernel A1: per-graph precompute (d0, w, z)
// ============================================================
__global__ void precompute_kernel(const float* __restrict__ U,
                                  const float* __restrict__ V,
                                  const float* __restrict__ XS,
                                  const float* __restrict__ AT,
                                  const float* __restrict__ XT) {
    int g = blockIdx.x, t = threadIdx.x;
    const float* Ug = U + (size_t)g * nS * RK;
    const float* Vg = V + (size_t)g * RK * nS;
    const float* Ag = AT + (size_t)g * nS * nS;
    const float* xs = XS + (size_t)g * nS * Dd;
    const float* xt = XT + (size_t)g * nS * Dd;

    __shared__ float VU[RK][RK];
    __shared__ float u1[RK], u2a[RK], u2[RK], sv[nS];

    if (t < nS) {
        const float4* row = (const float4*)(xs + t * Dd);
        float acc = 0.f;
        #pragma unroll
        for (int k = 0; k < Dd / 4; k++) {
            float4 v = row[k];
            acc += v.x * v.x + v.y * v.y + v.z * v.z + v.w * v.w;
        }
        g_d0S[g * nS + t] = sqrtf(acc + 1e-4f);
    } else if (t < 2 * nS) {
        int r = t - nS;
        const float4* row = (const float4*)(xt + r * Dd);
        float acc = 0.f;
        #pragma unroll
        for (int k = 0; k < Dd / 4; k++) {
            float4 v = row[k];
            acc += v.x * v.x + v.y * v.y + v.z * v.z + v.w * v.w;
        }
        g_d0T[g * nS + r] = sqrtf(acc + 1e-4f);
    }

    for (int e = t; e < RK * RK; e += blockDim.x) {
        int i = e / RK, j = e % RK;
        float acc = 0.f;
        for (int a = 0; a < nS; a++) acc += Vg[i * nS + a] * Ug[a * RK + j];
        VU[i][j] = acc;
    }
    __syncthreads();

    if (t < RK) {
        float acc = 0.f;
        for (int a = 0; a < nS; a++) acc += Ug[a * RK + t];
        u1[t] = acc;
    } else if (t < RK + nS) {
        int i = t - RK;
        float acc = 0.f;
        for (int j = 0; j < nS; j++) acc += Ag[j * nS + i];
        sv[i] = acc + 1e-4f;
    }
    __syncthreads();
    if (t < RK) {
        float acc = 0.f;
        for (int r = 0; r < RK; r++) acc += VU[r][t] * u1[r];
        u2a[t] = acc;
    }
    __syncthreads();
    if (t < RK) {
        float acc = 0.f;
        for (int r = 0; r < RK; r++) acc += VU[r][t] * u2a[r];
        u2[t] = acc;
    }
    __syncthreads();
    if (t < nS) {
        float acc = 0.f;
        for (int r = 0; r < RK; r++) acc += Vg[r * nS + t] * u2[r];
        g_w[g * nS + t] = acc;
    } else if (t < 2 * nS) {
        int i = t - nS;
        float acc = 0.f;
        for (int j = 0; j < nS; j++) acc += Ag[j * nS + i] * sv[j];
        g_z[g * nS + i] = acc + 1e-4f * sv[i];
    }
}

// ============================================================
// Kernel B: HMMA tile kernel with ldmatrix + fast NTK epilogue.
// ============================================================
__global__ void __launch_bounds__(256, 2)
mma_tile_kernel(float* __restrict__ KSS) {
    int bid = blockIdx.x;
    int ti, tj, isST;
    if (bid < NSS) {
        isST = 0;
        int rem = bid, cnt = 48;
        ti = 0;
        while (rem >= cnt) { rem -= cnt; ti++; cnt--; }
        tj = ti + rem;
    } else {
        isST = 1;
        int r = bid - NSS;
        ti = r / 48;
        tj = r - ti * 48;
    }

    extern __shared__ uint32_t smU[];
    uint32_t sbase = smem_u32(smU);
    int t = threadIdx.x;
    int w = t >> 5, lane = t & 31;
    int g2 = lane >> 2, tg = lane & 3;

    const uint4* ShiV = (const uint4*)g_Shi;
    const uint4* SloV = (const uint4*)g_Slo;
    const uint4* RhiV = isST ? (const uint4*)g_Thi : ShiV;
    const uint4* RloV = isST ? (const uint4*)g_Tlo : SloV;
    int rowL = ti * 96, rowR = tj * 96;

    for (int idx = t; idx < 96 * 16; idx += 256) {
        int r = idx >> 4, c4 = idx & 15;
        int so = r * LDU + c4 * 4;
        *(uint4*)(smU + AH_U + so) = ShiV[(size_t)(rowL + r) * 16 + c4];
        *(uint4*)(smU + AL_U + so) = SloV[(size_t)(rowL + r) * 16 + c4];
        *(uint4*)(smU + BH_U + so) = RhiV[(size_t)(rowR + r) * 16 + c4];
        *(uint4*)(smU + BL_U + so) = RloV[(size_t)(rowR + r) * 16 + c4];
    }
    float* dv = (float*)(smU + DV_U);
    for (int idx = t; idx < 384; idx += 256) {
        float v;
        if (idx < 96)        v = g_d0S[rowL + idx];
        else if (idx < 192)  v = g_w[rowL + idx - 96];
        else if (idx < 288)  v = (isST ? g_d0T : g_d0S)[rowR + idx - 192];
        else                 v = (isST ? g_z : g_w)[rowR + idx - 288];
        dv[idx] = v;
    }
    __syncthreads();

    int wr = w >> 2, wc = w & 3;
    int mrow0 = wr * 48, ncol0 = wc * 24;

    int l7 = lane & 7;
    uint32_t aoff = (uint32_t)((mrow0 + l7 + ((lane >> 3) & 1) * 8) * LDB +
                               ((lane >> 4) & 1) * 16);
    uint32_t boff01 = (uint32_t)((ncol0 + ((lane >> 4) & 1) * 8 + l7) * LDB +
                                 ((lane >> 3) & 1) * 16);
    uint32_t boff2 = (uint32_t)((ncol0 + 16 + l7) * LDB +
                                ((lane >> 3) & 1) * 16);

    float acc[3][3][4];
    #pragma unroll
    for (int mi = 0; mi < 3; mi++)
        #pragma unroll
        for (int nj = 0; nj < 3; nj++)
            #pragma unroll
            for (int e = 0; e < 4; e++) acc[mi][nj][e] = 0.f;

    #pragma unroll
    for (int s = 0; s < 3; s++) {
        uint32_t Ab = sbase + (uint32_t)((s == 2 ? AL_U : AH_U) * 4);
        uint32_t Bb = sbase + (uint32_t)((s == 1 ? BL_U : BH_U) * 4);
        #pragma unroll
        for (int ks = 0; ks < 8; ks++) {
            uint32_t kb = (uint32_t)(ks * 32);
            uint32_t b01[4], b2[2];
            ldmx4(b01, Bb + boff01 + kb);
            ldmx2(b2, Bb + boff2 + kb);
            #pragma unroll
            for (int mi = 0; mi < 3; mi++) {
                uint32_t a[4];
                ldmx4(a, Ab + aoff + (uint32_t)(mi * 16 * LDB) + kb);
                mma16816(acc[mi][0], a[0], a[1], a[2], a[3], b01[0], b01[1]);
                mma16816(acc[mi][1], a[0], a[1], a[2], a[3], b01[2], b01[3]);
                mma16816(acc[mi][2], a[0], a[1], a[2], a[3], b2[0], b2[1]);
            }
        }
    }

    // ---- fused NTK epilogue on register fragments ----
    const float PI_F = 3.14159265358979323846f;
    float thc = acosf(0.9999f);
    float c1 = (0.9999f * (PI_F - thc) + sqrtf(1.f - 0.9999f * 0.9999f)) / PI_F;
    float ic1 = 1.f / c1;

    const float* dL = dv;
    const float* wL = dv + 96;
    const float* dR = dv + 192;
    const float* vR = dv + 288;

    float partial = 0.f;
    #pragma unroll
    for (int mi = 0; mi < 3; mi++) {
        int r0 = mrow0 + mi * 16 + g2, r1 = r0 + 8;
        float da0 = dL[r0], wa0 = wL[r0];
        float da1 = dL[r1], wa1 = wL[r1];
        #pragma unroll
        for (int nj = 0; nj < 3; nj++) {
            int c0 = ncol0 + nj * 8 + tg * 2, c1i = c0 + 1;
            float db0 = dR[c0], vb0 = vR[c0];
            float db1 = dR[c1i], vb1 = vR[c1i];
            partial += wa0 * ntk_eval(acc[mi][nj][0], da0, db0, ic1) * vb0;
            partial += wa0 * ntk_eval(acc[mi][nj][1], da0, db1, ic1) * vb1;
            partial += wa1 * ntk_eval(acc[mi][nj][2], da1, db0, ic1) * vb0;
            partial += wa1 * ntk_eval(acc[mi][nj][3], da1, db1, ic1) * vb1;
        }
    }

    #pragma unroll
    for (int o = 16; o > 0; o >>= 1)
        partial += __shfl_down_sync(0xffffffffu, partial, o);
    float* wslot = (float*)(smU + WS_U);
    if (lane == 0) wslot[w] = partial;
    __syncthreads();

    if (t < 4) {
        int qi = t >> 1, qj = t & 1;
        int w0 = qi * 4 + qj * 2;
        float s = wslot[w0] + wslot[w0 + 1];
        int N = 2 * ti + qi, M = 2 * tj + qj;
        if (!isST) {
            if (!(ti == tj && qi > qj)) {
                KSS[N * Ng + M] = s;
                KSS[M * Ng + N] = s;
            }
        } else {
            g_KST[N * Ng + M] = s;
        }
    }
}

// ============================================================
// Kernel C: one-sync-per-iter Gauss-Jordan (SPD, no pivoting) + pred.
// Iter k reads {col k, row k}, writes {i!=k, j>k} -- disjoint sets,
// so a single barrier per iteration suffices.
// ============================================================
__global__ void solve_kernel(const float* __restrict__ yS,
                             const float* __restrict__ KSS,
                             float* __restrict__ out) {
    __shared__ float A[96][107];   // [K | y], odd stride
    __shared__ float rtr;
    int t = threadIdx.x;
    int j = t & 127, ig = t >> 7;

    for (int i = ig; i < 96; i += 4) {
        float v = 0.f;
        if (j < 96) v = KSS[i * 96 + j];
        else if (j < 106) v = yS[i * 10 + (j - 96)];
        if (j < 107) A[i][j] = v;
    }
    __syncthreads();

    if (t < 32) {
        float tr = 0.f;
        for (int i = t; i < 96; i += 32) tr += A[i][i];
        #pragma unroll
        for (int o = 16; o > 0; o >>= 1) tr += __shfl_down_sync(0xffffffffu, tr, o);
        if (t == 0) rtr = 1e-6f * tr / 96.f;
    }
    __syncthreads();
    if (t < 96) A[t][t] += rtr;
    __syncthreads();

    for (int k = 0; k < 96; k++) {
        if (j > k && j < 106) {
            float rp = __frcp_rn(A[k][k]);
            float f = A[k][j] * rp;
            #pragma unroll 8
            for (int i = ig; i < 96; i += 4)
                if (i != k) A[i][j] = fmaf(-A[i][k], f, A[i][j]);
        }
        __syncthreads();
    }

    // alpha = rhs / diag, then pred = K_ST^T @ alpha
    for (int idx = t; idx < 960; idx += 512) {
        int i = idx / 10, c = idx - i * 10;
        A[i][96 + c] /= A[i][i];
    }
    __syncthreads();

    for (int idx = t; idx < 960; idx += 512) {
        int m = idx / 10, c = idx - m * 10;
        float acc = 0.f;
        for (int n2 = 0; n2 < 96; n2++)
            acc += g_KST[n2 * 96 + m] * A[n2][96 + c];
        out[idx] = acc;
    }
}

// ============================================================
extern "C" void kernel_launch(void* const* d_in, const int* in_sizes, int n_in,
                              void* d_out, int out_size) {
    const float* U  = (const float*)d_in[0];
    const float* V  = (const float*)d_in[1];
    const float* XS = (const float*)d_in[2];
    const float* yS = (const float*)d_in[3];
    const float* AT = (const float*)d_in[4];
    const float* XT = (const float*)d_in[5];
    float* out = (float*)d_out;   // [pred (96,10) | K_SS (96,96)]
    float* KSS = out + Ng * Cc;

    split_kernel<<<(Ng * nS * Dd / 4 + 255) / 256, 256>>>(XS, XT);
    precompute_kernel<<<Ng, 128>>>(U, V, XS, AT, XT);

    cudaFuncSetAttribute(mma_tile_kernel, cudaFuncAttributeMaxDynamicSharedMemorySize,
                         SMEM_BYTES);
    mma_tile_kernel<<<NTILES, 256, SMEM_BYTES>>>(KSS);

    solve_kernel<<<1, 512>>>(yS, KSS, out);
}